// round 13
// baseline (speedup 1.0000x reference)
#include <cuda_runtime.h>
#include <cuda_fp16.h>
#include <math.h>
#include <stdint.h>

// ---------------- problem constants ----------------
#define NN    100000
#define UU    50000
#define DD    64
#define LEAK  0.2f
#define RIS_ADJ_LAMBDA 0.2f
#define RIS_LAMBDA     0.5f

#define CAP   80              // per-row bucket capacity (Poisson(32): P(>=80) ~ 1e-11)
#define NPART 64
#define FULL  0xffffffffu
#define PAIRB 6250

// ---------------- static scratch ----------------
__device__ __half g_e0h  [(size_t)NN*DD];
__device__ __half g_e1h  [(size_t)NN*DD];
__device__ __half g_Xth  [(size_t)NN*DD];
__device__ __half g_mh   [(size_t)NN*DD];
__device__ __half g_ch   [(size_t)NN*DD];   // layer output (doubles as lay1 term)
__device__ __half g_Eh   [(size_t)NN*DD];   // pre-activation spmm result (fp16)
__device__ float g_XimgI[(size_t)UU*DD];
__device__ float g_P    [(size_t)NN*DD];
__device__ float g_modal[(size_t)NN*DD];
__device__ float g_scores[NN];
__device__ float g_redpart[2*NPART];
__device__ int   g_cnt  [3*NN];                       // zeroed each replay
__device__ int2  g_colval[(size_t)3*NN*CAP];          // capacity-padded CSR

// ---------------- helpers ----------------
__device__ __forceinline__ uint32_t smem_u32(const void* p) {
    return (uint32_t)__cvta_generic_to_shared(p);
}
__device__ __forceinline__ void ldm_x4(uint32_t& r0, uint32_t& r1,
                                       uint32_t& r2, uint32_t& r3, uint32_t a) {
    asm volatile("ldmatrix.sync.aligned.m8n8.x4.shared.b16 {%0,%1,%2,%3}, [%4];"
                 : "=r"(r0), "=r"(r1), "=r"(r2), "=r"(r3) : "r"(a));
}
__device__ __forceinline__ void ldm_x2t(uint32_t& r0, uint32_t& r1, uint32_t a) {
    asm volatile("ldmatrix.sync.aligned.m8n8.x2.trans.shared.b16 {%0,%1}, [%2];"
                 : "=r"(r0), "=r"(r1) : "r"(a));
}
__device__ __forceinline__ void mma16816(float* c, const uint32_t* a, const uint32_t* b) {
    asm volatile("mma.sync.aligned.m16n8k16.row.col.f32.f16.f16.f32 "
                 "{%0,%1,%2,%3}, {%4,%5,%6,%7}, {%8,%9}, {%0,%1,%2,%3};"
                 : "+f"(c[0]), "+f"(c[1]), "+f"(c[2]), "+f"(c[3])
                 : "r"(a[0]), "r"(a[1]), "r"(a[2]), "r"(a[3]), "r"(b[0]), "r"(b[1]));
}
__device__ __forceinline__ void msmerge(float& m, float& s, float m2, float s2) {
    float M = fmaxf(m, m2);
    s = s * expf(m - M) + s2 * expf(m2 - M);
    m = M;
}
__device__ __forceinline__ float4 h8_to_f4(uint2 r) {
    float2 lo = __half22float2(*(__half2*)&r.x);
    float2 hi = __half22float2(*(__half2*)&r.y);
    return make_float4(lo.x, lo.y, hi.x, hi.y);
}
__device__ __forceinline__ uint2 f4_to_h8(float4 v) {
    uint2 h;
    *(__half2*)&h.x = __float22half2_rn(make_float2(v.x, v.y));
    *(__half2*)&h.y = __float22half2_rn(make_float2(v.z, v.w));
    return h;
}

// ---------------- HMMA GEMM body (uses caller smem) ----------------
__device__ __forceinline__ void gemm_body(const float* __restrict__ A,
                                          const float* __restrict__ W,
                                          const float* __restrict__ bias,
                                          float* __restrict__ dstf,
                                          __half* __restrict__ dsth,
                                          int M, int K, int blk,
                                          __half* As, __half* Ws, float* Cs) {
    const int tid = threadIdx.x;
    const int wid = tid >> 5, lane = tid & 31;
    const int wm = wid >> 1, wn = wid & 1;
    const int rowBase = blk * 128;

    float acc[2][4][4];
    #pragma unroll
    for (int i = 0; i < 2; i++)
        #pragma unroll
        for (int j = 0; j < 4; j++)
            #pragma unroll
            for (int k = 0; k < 4; k++) acc[i][j][k] = 0.f;

    const int ra = tid >> 1, ha = tid & 1;
    const int rw = tid >> 3, sw = tid & 7;
    const bool avalid = (rowBase + ra) < M;

    for (int kc = 0; kc < K; kc += 32) {
        const float* ap = A + (size_t)(rowBase + ra) * K + kc + ha * 16;
        #pragma unroll
        for (int q = 0; q < 4; q++) {
            float4 f = avalid ? *(const float4*)(ap + q * 4)
                              : make_float4(0.f, 0.f, 0.f, 0.f);
            __half2* d = (__half2*)&As[ra * 40 + ha * 16 + q * 4];
            d[0] = __floats2half2_rn(f.x, f.y);
            d[1] = __floats2half2_rn(f.z, f.w);
        }
        const float* wp = W + (size_t)(kc + rw) * DD + sw * 8;
        #pragma unroll
        for (int q = 0; q < 2; q++) {
            float4 f = *(const float4*)(wp + q * 4);
            __half2* d = (__half2*)&Ws[rw * 72 + sw * 8 + q * 4];
            d[0] = __floats2half2_rn(f.x, f.y);
            d[1] = __floats2half2_rn(f.z, f.w);
        }
        __syncthreads();
        #pragma unroll
        for (int ks = 0; ks < 2; ks++) {
            uint32_t afr[2][4];
            #pragma unroll
            for (int mm = 0; mm < 2; mm++) {
                int mrow = wm * 32 + mm * 16 + (lane & 15);
                int kcol = ks * 16 + ((lane >> 4) << 3);
                ldm_x4(afr[mm][0], afr[mm][1], afr[mm][2], afr[mm][3],
                       smem_u32(&As[mrow * 40 + kcol]));
            }
            uint32_t bfr[4][2];
            #pragma unroll
            for (int nn = 0; nn < 4; nn++) {
                int krow = ks * 16 + (lane & 15);
                int ncol = wn * 32 + nn * 8;
                ldm_x2t(bfr[nn][0], bfr[nn][1], smem_u32(&Ws[krow * 72 + ncol]));
            }
            #pragma unroll
            for (int mm = 0; mm < 2; mm++)
                #pragma unroll
                for (int nn = 0; nn < 4; nn++)
                    mma16816(acc[mm][nn], afr[mm], bfr[nn]);
        }
        __syncthreads();
    }

    #pragma unroll
    for (int mm = 0; mm < 2; mm++) {
        int r0 = wm * 32 + mm * 16 + (lane >> 2);
        #pragma unroll
        for (int nn = 0; nn < 4; nn++) {
            int c0 = wn * 32 + nn * 8 + (lane & 3) * 2;
            *(float2*)&Cs[r0 * 66 + c0]       = make_float2(acc[mm][nn][0], acc[mm][nn][1]);
            *(float2*)&Cs[(r0 + 8) * 66 + c0] = make_float2(acc[mm][nn][2], acc[mm][nn][3]);
        }
    }
    __syncthreads();

    float2 bv = *(const float2*)&bias[lane * 2];
    #pragma unroll
    for (int i = 0; i < 16; i++) {
        int r = wid * 16 + i;
        int g = rowBase + r;
        if (g >= M) break;
        float2 v = *(const float2*)&Cs[r * 66 + lane * 2];
        v.x += bv.x; v.y += bv.y;
        float ss = v.x * v.x + v.y * v.y;
        #pragma unroll
        for (int o = 16; o; o >>= 1) ss += __shfl_xor_sync(FULL, ss, o);
        float inv = 1.f / fmaxf(sqrtf(ss), 1e-12f);
        size_t off = (size_t)g * DD + lane * 2;
        if (dstf) *(float2*)&dstf[off] = make_float2(v.x * inv, v.y * inv);
        if (dsth) *(__half2*)&dsth[off] =
            __float22half2_rn(make_float2(v.x * inv, v.y * inv));
    }
}

// ---------------- launch 2: FUSED build kernel ----------------
__global__ void k_build(const float* __restrict__ A1, const float* __restrict__ W1,
                        const float* __restrict__ b1, float* __restrict__ XimgI,
                        const float* __restrict__ A2, const float* __restrict__ W2,
                        const float* __restrict__ b2, __half* __restrict__ XthI,
                        int nb1,
                        const int* __restrict__ ar, const int* __restrict__ ac,
                        const float* __restrict__ av,
                        const int* __restrict__ ir, const int* __restrict__ ic,
                        const float* __restrict__ iv,
                        const int* __restrict__ tr, const int* __restrict__ tc,
                        const float* __restrict__ tv,
                        int* __restrict__ cnt, int2* __restrict__ colval,
                        int e0, int e1, int e2,
                        const float* __restrict__ u, const float* __restrict__ it,
                        __half* __restrict__ e0h, __half* __restrict__ e1h,
                        __half* __restrict__ Xth) {
    __shared__ __align__(16) char smu[33792];
    int b = blockIdx.x;
    if (b < 2 * nb1) {
        __half* As = (__half*)smu;
        __half* Ws = (__half*)(smu + 10240);
        float*  Cs = (float*)smu;
        if (b < nb1)
            gemm_body(A1, W1, b1, XimgI, (half*)nullptr, UU, 1024, b, As, Ws, Cs);
        else
            gemm_body(A2, W2, b2, (float*)nullptr, XthI, UU, 384, b - nb1, As, Ws, Cs);
        return;
    }
    int i = (b - 2 * nb1) * blockDim.x + threadIdx.x;
    if (i < e0) {
        int r = ar[i];
        int p = atomicAdd(&cnt[0 * NN + r], 1);
        if (p < CAP)
            colval[(size_t)(0 * NN + r) * CAP + p] = make_int2(ac[i], __float_as_int(av[i]));
    }
    if (i < e1) {
        int r = ir[i];
        int p = atomicAdd(&cnt[1 * NN + r], 1);
        if (p < CAP)
            colval[(size_t)(1 * NN + r) * CAP + p] = make_int2(ic[i], __float_as_int(iv[i]));
    }
    if (i < e2) {
        int r = tr[i];
        int p = atomicAdd(&cnt[2 * NN + r], 1);
        if (p < CAP)
            colval[(size_t)(2 * NN + r) * CAP + p] = make_int2(tc[i], __float_as_int(tv[i]));
    }
    size_t idx2 = (size_t)i;
    if (idx2 < (size_t)NN * DD / 2) {
        size_t idx = idx2 * 2;
        int n = (int)(idx >> 6);
        if (n < UU) {
            __half2 h = __float22half2_rn(*(const float2*)(u + idx));
            *(__half2*)(e0h + idx) = h;
            *(__half2*)(Xth + idx) = h;
        } else {
            __half2 h = __float22half2_rn(*(const float2*)(it + idx - (size_t)UU * DD));
            *(__half2*)(e0h + idx) = h;
            *(__half2*)(e1h + idx) = h;
        }
    }
}

// ---------------- SpMM core: half-warp per row, float4/lane, pair early-exit --
__device__ __forceinline__ float4 spmm16(const int2* __restrict__ colval,
                                         const __half* __restrict__ x,
                                         int s, int len, int mlen, int sub) {
    float4 a0 = make_float4(0.f, 0.f, 0.f, 0.f);
    float4 a1 = make_float4(0.f, 0.f, 0.f, 0.f);
    for (int k = 0; k < mlen; k += 16) {
        int2 cv = (k + sub < len) ? colval[s + k + sub] : make_int2(0, 0);
        #pragma unroll
        for (int j = 0; j < 16; j += 2) {
            if (k + j >= mlen) break;          // warp-uniform: mlen is warp-uniform
            int   c0 = __shfl_sync(FULL, cv.x, j, 16);
            float v0 = __int_as_float(__shfl_sync(FULL, cv.y, j, 16));
            int   c1 = __shfl_sync(FULL, cv.x, j + 1, 16);
            float v1 = __int_as_float(__shfl_sync(FULL, cv.y, j + 1, 16));
            float4 x0 = h8_to_f4(*(const uint2*)(x + (size_t)c0 * DD + sub * 4));
            float4 x1 = h8_to_f4(*(const uint2*)(x + (size_t)c1 * DD + sub * 4));
            a0.x = fmaf(v0, x0.x, a0.x); a0.y = fmaf(v0, x0.y, a0.y);
            a0.z = fmaf(v0, x0.z, a0.z); a0.w = fmaf(v0, x0.w, a0.w);
            a1.x = fmaf(v1, x1.x, a1.x); a1.y = fmaf(v1, x1.y, a1.y);
            a1.z = fmaf(v1, x1.z, a1.z); a1.w = fmaf(v1, x1.w, a1.w);
        }
    }
    return make_float4(a0.x + a1.x, a0.y + a1.y, a0.z + a1.z, a0.w + a1.w);
}

// ---------------- launch 3: modality spmms, fused to partial P ---------------
__global__ void k_spmm_modal(const int* __restrict__ cnt, const int2* __restrict__ colval,
                             const __half* __restrict__ e0h, const __half* __restrict__ Xth,
                             const float* __restrict__ u, const float* __restrict__ XimgI,
                             const float* __restrict__ mw,
                             float* __restrict__ P, __half* __restrict__ e1h) {
    int pair = (blockIdx.x * blockDim.x + threadIdx.x) >> 5;
    if (pair >= NN / 2) return;
    const int lane = threadIdx.x & 31;
    const int half = lane >> 4, sub = lane & 15;
    int row = pair * 2 + half;

    int len = min(cnt[1 * NN + row], CAP);
    int mlen = max(len, __shfl_xor_sync(FULL, len, 16));
    float4 s1 = spmm16(colval, e0h, (1 * NN + row) * CAP, len, mlen, sub);
    len = min(cnt[2 * NN + row], CAP);
    mlen = max(len, __shfl_xor_sync(FULL, len, 16));
    float4 s3 = spmm16(colval, e0h, (2 * NN + row) * CAP, len, mlen, sub);

    len = min(cnt[row], CAP);
    mlen = max(len, __shfl_xor_sync(FULL, len, 16));
    int s = row * CAP;
    float4 p0 = make_float4(0.f,0.f,0.f,0.f), p1 = p0, q0 = p0, q1 = p0;
    for (int k = 0; k < mlen; k += 16) {
        int2 cvv = (k + sub < len) ? colval[(size_t)s + k + sub] : make_int2(0, 0);
        #pragma unroll
        for (int j = 0; j < 16; j += 2) {
            if (k + j >= mlen) break;          // warp-uniform
            int   c0 = __shfl_sync(FULL, cvv.x, j, 16);
            float v0 = __int_as_float(__shfl_sync(FULL, cvv.y, j, 16));
            int   c1 = __shfl_sync(FULL, cvv.x, j + 1, 16);
            float v1 = __int_as_float(__shfl_sync(FULL, cvv.y, j + 1, 16));
            size_t o0 = (size_t)c0 * DD + sub * 4;
            size_t o1 = (size_t)c1 * DD + sub * 4;
            float4 a0 = h8_to_f4(*(const uint2*)(e0h + o0));
            float4 a1 = h8_to_f4(*(const uint2*)(e0h + o1));
            float4 b0 = (c0 < UU) ? a0 : h8_to_f4(*(const uint2*)(Xth + o0));
            float4 b1 = (c1 < UU) ? a1 : h8_to_f4(*(const uint2*)(Xth + o1));
            p0.x = fmaf(v0, a0.x, p0.x); p0.y = fmaf(v0, a0.y, p0.y);
            p0.z = fmaf(v0, a0.z, p0.z); p0.w = fmaf(v0, a0.w, p0.w);
            p1.x = fmaf(v1, a1.x, p1.x); p1.y = fmaf(v1, a1.y, p1.y);
            p1.z = fmaf(v1, a1.z, p1.z); p1.w = fmaf(v1, a1.w, p1.w);
            q0.x = fmaf(v0, b0.x, q0.x); q0.y = fmaf(v0, b0.y, q0.y);
            q0.z = fmaf(v0, b0.z, q0.z); q0.w = fmaf(v0, b0.w, q0.w);
            q1.x = fmaf(v1, b1.x, q1.x); q1.y = fmaf(v1, b1.y, q1.y);
            q1.z = fmaf(v1, b1.z, q1.z); q1.w = fmaf(v1, b1.w, q1.w);
        }
    }
    float4 s2 = make_float4(p0.x + p1.x, p0.y + p1.y, p0.z + p1.z, p0.w + p1.w);
    float4 t1 = make_float4(q0.x + q1.x, q0.y + q1.y, q0.z + q1.z, q0.w + q1.w);

    float a = mw[0], b = mw[1];
    float mx = fmaxf(a, b);
    float ea = expf(a - mx), eb = expf(b - mx);
    float w0 = ea / (ea + eb), w1 = eb / (ea + eb);
    size_t off = (size_t)row * DD + sub * 4;
    float4 xi = (row < UU) ? *(const float4*)(u + off)
                           : *(const float4*)(XimgI + off - (size_t)UU * DD);
    float4 pv;
    pv.x = w0 * (xi.x + s2.x + RIS_ADJ_LAMBDA * s1.x) + w1 * (t1.x + RIS_ADJ_LAMBDA * s3.x);
    pv.y = w0 * (xi.y + s2.y + RIS_ADJ_LAMBDA * s1.y) + w1 * (t1.y + RIS_ADJ_LAMBDA * s3.y);
    pv.z = w0 * (xi.z + s2.z + RIS_ADJ_LAMBDA * s1.z) + w1 * (t1.z + RIS_ADJ_LAMBDA * s3.z);
    pv.w = w0 * (xi.w + s2.w + RIS_ADJ_LAMBDA * s1.w) + w1 * (t1.w + RIS_ADJ_LAMBDA * s3.w);
    *(float4*)(P + off) = pv;
    if (row < UU) *(uint2*)(e1h + off) = f4_to_h8(t1);
}

// ---------------- launch 4: T2 spmm + final modal ----------------------------
__global__ void k_spmmT2_modal(const int* __restrict__ cnt,
                               const int2* __restrict__ colval,
                               const __half* __restrict__ x,
                               const float* __restrict__ P,
                               const float* __restrict__ mw,
                               float* __restrict__ modal,
                               __half* __restrict__ modalh) {
    int pair = (blockIdx.x * blockDim.x + threadIdx.x) >> 5;
    if (pair >= NN / 2) return;
    const int lane = threadIdx.x & 31;
    const int half = lane >> 4, sub = lane & 15;
    int row = pair * 2 + half;
    int len = min(cnt[row], CAP);
    int mlen = max(len, __shfl_xor_sync(FULL, len, 16));
    float4 t2 = spmm16(colval, x, row * CAP, len, mlen, sub);

    float a = mw[0], b = mw[1];
    float mx = fmaxf(a, b);
    float ea = expf(a - mx), eb = expf(b - mx);
    float w1 = eb / (ea + eb);

    size_t off = (size_t)row * DD + sub * 4;
    float4 pv = *(const float4*)(P + off);
    float4 m = make_float4(pv.x + w1 * t2.x, pv.y + w1 * t2.y,
                           pv.z + w1 * t2.z, pv.w + w1 * t2.w);
    *(float4*)(modal + off) = m;
    *(uint2*)(modalh + off) = f4_to_h8(m);
}

// ---------------- GNN spmm: y(fp16) = adj@x + attention scores ----------------
__global__ void k_spmm(const int* __restrict__ cnt, const int2* __restrict__ colval,
                       const __half* __restrict__ x, __half* __restrict__ y,
                       const float* __restrict__ attw, float* __restrict__ scores) {
    int pair = (blockIdx.x * blockDim.x + threadIdx.x) >> 5;
    if (pair >= NN / 2) return;
    const int lane = threadIdx.x & 31;
    const int half = lane >> 4, sub = lane & 15;
    int row = pair * 2 + half;
    int len = min(cnt[row], CAP);
    int mlen = max(len, __shfl_xor_sync(FULL, len, 16));
    float4 acc = spmm16(colval, x, row * CAP, len, mlen, sub);
    *(uint2*)(y + (size_t)row * DD + sub * 4) = f4_to_h8(acc);
    float4 aw = *(const float4*)(attw + sub * 4);
    float sc = acc.x * aw.x + acc.y * aw.y + acc.z * aw.z + acc.w * aw.w;
    #pragma unroll
    for (int o = 8; o; o >>= 1) sc += __shfl_xor_sync(FULL, sc, o, 16);
    if (sub == 0) scores[row] = sc;
}

// ---------------- softmax partials ----------------
__global__ void k_redpart(const float* __restrict__ scores, float* __restrict__ part) {
    const int tid = threadIdx.x, lane = tid & 31, wid = tid >> 5;
    float m = -3.4e38f, s = 0.f;
    for (int i = blockIdx.x * blockDim.x + tid; i < NN; i += gridDim.x * blockDim.x) {
        float x = scores[i];
        float M = fmaxf(m, x);
        s = s * expf(m - M) + expf(x - M);
        m = M;
    }
    #pragma unroll
    for (int o = 16; o; o >>= 1) {
        float m2 = __shfl_xor_sync(FULL, m, o);
        float s2 = __shfl_xor_sync(FULL, s, o);
        msmerge(m, s, m2, s2);
    }
    __shared__ float sm[8], ssum[8];
    if (lane == 0) { sm[wid] = m; ssum[wid] = s; }
    __syncthreads();
    if (tid == 0) {
        float M = sm[0], S = ssum[0];
        #pragma unroll
        for (int w = 1; w < 8; w++) msmerge(M, S, sm[w], ssum[w]);
        part[blockIdx.x * 2]     = M;
        part[blockIdx.x * 2 + 1] = S;
    }
}

__device__ __forceinline__ void merge_partials(const float* __restrict__ part,
                                               float& M, float& S,
                                               float* sMS, int tid) {
    if (tid < 32) {
        float m = -3.4e38f, s = 0.f;
        #pragma unroll
        for (int i = tid; i < NPART; i += 32)
            msmerge(m, s, part[i * 2], part[i * 2 + 1]);
        #pragma unroll
        for (int o = 16; o; o >>= 1) {
            float m2 = __shfl_xor_sync(FULL, m, o);
            float s2 = __shfl_xor_sync(FULL, s, o);
            msmerge(m, s, m2, s2);
        }
        if (tid == 0) { sMS[0] = m; sMS[1] = s; }
    }
    __syncthreads();
    M = sMS[0]; S = sMS[1];
}

// layer-1 apply: ch = half(leakyrelu(E*att)); 4 halves/thread
__global__ void k_apply(const __half* __restrict__ e, const float* __restrict__ scores,
                        const float* __restrict__ part, __half* __restrict__ curh) {
    __shared__ float sMS[2];
    float M, S;
    merge_partials(part, M, S, sMS, threadIdx.x);
    size_t i4 = (size_t)blockIdx.x * blockDim.x + threadIdx.x;
    if (i4 >= (size_t)NN * DD / 4) return;
    size_t idx = i4 * 4;
    int n = (int)(idx >> 6);
    float att = expf(scores[n] - M) / S;
    float4 v = h8_to_f4(*(const uint2*)(e + idx));
    v.x *= att; v.x = (v.x > 0.f) ? v.x : LEAK * v.x;
    v.y *= att; v.y = (v.y > 0.f) ? v.y : LEAK * v.y;
    v.z *= att; v.z = (v.z > 0.f) ? v.z : LEAK * v.z;
    v.w *= att; v.w = (v.w > 0.f) ? v.w : LEAK * v.w;
    *(uint2*)(curh + idx) = f4_to_h8(v);
}

// layer-2 apply fused with final output: out = modal + lay1(=ch) + v2 + l*l2n(modal)
__global__ void k_apply2_final(const __half* __restrict__ e, const float* __restrict__ scores,
                               const float* __restrict__ part,
                               const __half* __restrict__ lay1,
                               const float* __restrict__ modal,
                               float* __restrict__ out) {
    __shared__ float sMS[2];
    float M, S;
    merge_partials(part, M, S, sMS, threadIdx.x);
    int row = (blockIdx.x * blockDim.x + threadIdx.x) >> 5;
    if (row >= NN) return;
    const int lane = threadIdx.x & 31;
    size_t off = (size_t)row * DD + lane * 2;
    float att = expf(scores[row] - M) / S;
    float2 ev = __half22float2(*(const __half2*)(e + off));
    float vx = ev.x * att; vx = (vx > 0.f) ? vx : LEAK * vx;
    float vy = ev.y * att; vy = (vy > 0.f) ? vy : LEAK * vy;
    float2 l1 = __half22float2(*(const __half2*)(lay1 + off));
    float2 m = *(const float2*)(modal + off);
    float ss = m.x * m.x + m.y * m.y;
    #pragma unroll
    for (int o = 16; o; o >>= 1) ss += __shfl_xor_sync(FULL, ss, o);
    float inv = 1.f / fmaxf(sqrtf(ss), 1e-12f);
    *(float2*)(out + off) = make_float2(m.x + l1.x + vx + RIS_LAMBDA * m.x * inv,
                                        m.y + l1.y + vy + RIS_LAMBDA * m.y * inv);
}

// ---------------- host ----------------
extern "C" void kernel_launch(void* const* d_in, const int* in_sizes, int n_in,
                              void* d_out, int out_size) {
    const int*   adj_rows = (const int*)d_in[0];
    const int*   adj_cols = (const int*)d_in[1];
    const float* adj_vals = (const float*)d_in[2];
    const int*   img_rows = (const int*)d_in[3];
    const int*   img_cols = (const int*)d_in[4];
    const float* img_vals = (const float*)d_in[5];
    const int*   txt_rows = (const int*)d_in[6];
    const int*   txt_cols = (const int*)d_in[7];
    const float* txt_vals = (const float*)d_in[8];
    const float* u_emb    = (const float*)d_in[9];
    const float* i_emb    = (const float*)d_in[10];
    const float* img_W    = (const float*)d_in[11];
    const float* img_b    = (const float*)d_in[12];
    const float* txt_W    = (const float*)d_in[13];
    const float* txt_b    = (const float*)d_in[14];
    const float* modal_w  = (const float*)d_in[15];
    const float* att_w    = (const float*)d_in[16];
    const float* image_embedding = (const float*)d_in[17];
    const float* text_embedding  = (const float*)d_in[18];

    const int Eadj = in_sizes[0], Eimg = in_sizes[3], Etxt = in_sizes[6];
    int Emx = Eadj > Eimg ? Eadj : Eimg;
    if (Etxt > Emx) Emx = Etxt;
    long long fuse_n = (long long)NN * DD / 2;
    if ((long long)Emx > fuse_n) fuse_n = Emx;

    __half *e0h, *e1h, *Xth, *mh, *ch, *Eh;
    float *XimgI, *P, *modal;
    float *scores, *part;
    int *cnt;
    int2 *colval;
    cudaGetSymbolAddress((void**)&e0h,   g_e0h);
    cudaGetSymbolAddress((void**)&e1h,   g_e1h);
    cudaGetSymbolAddress((void**)&Xth,   g_Xth);
    cudaGetSymbolAddress((void**)&mh,    g_mh);
    cudaGetSymbolAddress((void**)&ch,    g_ch);
    cudaGetSymbolAddress((void**)&Eh,    g_Eh);
    cudaGetSymbolAddress((void**)&XimgI, g_XimgI);
    cudaGetSymbolAddress((void**)&P,     g_P);
    cudaGetSymbolAddress((void**)&modal, g_modal);
    cudaGetSymbolAddress((void**)&scores,g_scores);
    cudaGetSymbolAddress((void**)&part,  g_redpart);
    cudaGetSymbolAddress((void**)&cnt,   g_cnt);
    cudaGetSymbolAddress((void**)&colval,g_colval);

    const int TPB = 256;
    const int ew4_blocks   = (NN * DD / 4 + TPB - 1) / TPB;   // 6250
    const int row_blocks   = (NN * 32 + TPB - 1) / TPB;
    const int fuse_blocks  = (int)((fuse_n + TPB - 1) / TPB);
    const int nb1 = (UU + 127) / 128;

    // 1: zero slot counters (replay determinism)
    cudaMemsetAsync(cnt, 0, 3 * NN * sizeof(int));
    // 2: FUSED build: 2 GEMMs + scatter/concat
    k_build<<<2 * nb1 + fuse_blocks, TPB>>>(
        image_embedding, img_W, img_b, XimgI,
        text_embedding, txt_W, txt_b, Xth + (size_t)UU * DD, nb1,
        adj_rows, adj_cols, adj_vals,
        img_rows, img_cols, img_vals,
        txt_rows, txt_cols, txt_vals,
        cnt, colval, Eadj, Eimg, Etxt,
        u_emb, i_emb, e0h, e1h, Xth);
    // 3: modality spmms fused to partial P (+ e1h)
    k_spmm_modal<<<PAIRB, TPB>>>(cnt, colval, e0h, Xth, u_emb, XimgI,
                                 modal_w, P, e1h);
    // 4: T2 spmm + final modal (+ mh)
    k_spmmT2_modal<<<PAIRB, TPB>>>(cnt, colval, e1h, P, modal_w, modal, mh);
    // 5-7: GNN layer 1
    k_spmm<<<PAIRB, TPB>>>(cnt, colval, mh, Eh, att_w + 0, scores);
    k_redpart<<<NPART, 256>>>(scores, part);
    k_apply<<<ew4_blocks, TPB>>>(Eh, scores, part, ch);
    // 8-10: GNN layer 2 + fused final
    k_spmm<<<PAIRB, TPB>>>(cnt, colval, ch, Eh, att_w + DD, scores);
    k_redpart<<<NPART, 256>>>(scores, part);
    k_apply2_final<<<row_blocks, TPB>>>(Eh, scores, part, ch, modal, (float*)d_out);
}

// round 14
// speedup vs baseline: 1.0371x; 1.0371x over previous
#include <cuda_runtime.h>
#include <cuda_fp16.h>
#include <math.h>
#include <stdint.h>

// ---------------- problem constants ----------------
#define NN    100000
#define UU    50000
#define DD    64
#define LEAK  0.2f
#define RIS_ADJ_LAMBDA 0.2f
#define RIS_LAMBDA     0.5f

#define CAP   80              // adj bucket capacity (Poisson(32): P(>=80) ~ 1e-11)
#define CAPC  160             // combined img+txt bucket capacity (Poisson(64))
#define NPART 64
#define FULL  0xffffffffu
#define PAIRB 6250

// ---------------- static scratch ----------------
__device__ __half g_e0h  [(size_t)NN*DD];
__device__ __half g_e1h  [(size_t)NN*DD];
__device__ __half g_Xth  [(size_t)NN*DD];
__device__ __half g_mh   [(size_t)NN*DD];
__device__ __half g_ch   [(size_t)NN*DD];   // layer output (doubles as lay1 term)
__device__ __half g_Eh   [(size_t)NN*DD];   // pre-activation spmm result (fp16)
__device__ float g_XimgI[(size_t)UU*DD];
__device__ float g_P    [(size_t)NN*DD];
__device__ float g_modal[(size_t)NN*DD];
__device__ float g_scores[NN];
__device__ float g_redpart[2*NPART];
__device__ int   g_cnt  [2*NN];                       // [0,NN)=adj, [NN,2NN)=combined
__device__ int2  g_colval[(size_t)NN*(CAP+CAPC)];     // adj then combined buckets

// ---------------- helpers ----------------
__device__ __forceinline__ uint32_t smem_u32(const void* p) {
    return (uint32_t)__cvta_generic_to_shared(p);
}
__device__ __forceinline__ void ldm_x4(uint32_t& r0, uint32_t& r1,
                                       uint32_t& r2, uint32_t& r3, uint32_t a) {
    asm volatile("ldmatrix.sync.aligned.m8n8.x4.shared.b16 {%0,%1,%2,%3}, [%4];"
                 : "=r"(r0), "=r"(r1), "=r"(r2), "=r"(r3) : "r"(a));
}
__device__ __forceinline__ void ldm_x2t(uint32_t& r0, uint32_t& r1, uint32_t a) {
    asm volatile("ldmatrix.sync.aligned.m8n8.x2.trans.shared.b16 {%0,%1}, [%2];"
                 : "=r"(r0), "=r"(r1) : "r"(a));
}
__device__ __forceinline__ void mma16816(float* c, const uint32_t* a, const uint32_t* b) {
    asm volatile("mma.sync.aligned.m16n8k16.row.col.f32.f16.f16.f32 "
                 "{%0,%1,%2,%3}, {%4,%5,%6,%7}, {%8,%9}, {%0,%1,%2,%3};"
                 : "+f"(c[0]), "+f"(c[1]), "+f"(c[2]), "+f"(c[3])
                 : "r"(a[0]), "r"(a[1]), "r"(a[2]), "r"(a[3]), "r"(b[0]), "r"(b[1]));
}
__device__ __forceinline__ void msmerge(float& m, float& s, float m2, float s2) {
    float M = fmaxf(m, m2);
    s = s * expf(m - M) + s2 * expf(m2 - M);
    m = M;
}
__device__ __forceinline__ float4 h8_to_f4(uint2 r) {
    float2 lo = __half22float2(*(__half2*)&r.x);
    float2 hi = __half22float2(*(__half2*)&r.y);
    return make_float4(lo.x, lo.y, hi.x, hi.y);
}
__device__ __forceinline__ uint2 f4_to_h8(float4 v) {
    uint2 h;
    *(__half2*)&h.x = __float22half2_rn(make_float2(v.x, v.y));
    *(__half2*)&h.y = __float22half2_rn(make_float2(v.z, v.w));
    return h;
}

// ---------------- HMMA GEMM body (uses caller smem) ----------------
__device__ __forceinline__ void gemm_body(const float* __restrict__ A,
                                          const float* __restrict__ W,
                                          const float* __restrict__ bias,
                                          float* __restrict__ dstf,
                                          __half* __restrict__ dsth,
                                          int M, int K, int blk,
                                          __half* As, __half* Ws, float* Cs) {
    const int tid = threadIdx.x;
    const int wid = tid >> 5, lane = tid & 31;
    const int wm = wid >> 1, wn = wid & 1;
    const int rowBase = blk * 128;

    float acc[2][4][4];
    #pragma unroll
    for (int i = 0; i < 2; i++)
        #pragma unroll
        for (int j = 0; j < 4; j++)
            #pragma unroll
            for (int k = 0; k < 4; k++) acc[i][j][k] = 0.f;

    const int ra = tid >> 1, ha = tid & 1;
    const int rw = tid >> 3, sw = tid & 7;
    const bool avalid = (rowBase + ra) < M;

    for (int kc = 0; kc < K; kc += 32) {
        const float* ap = A + (size_t)(rowBase + ra) * K + kc + ha * 16;
        #pragma unroll
        for (int q = 0; q < 4; q++) {
            float4 f = avalid ? *(const float4*)(ap + q * 4)
                              : make_float4(0.f, 0.f, 0.f, 0.f);
            __half2* d = (__half2*)&As[ra * 40 + ha * 16 + q * 4];
            d[0] = __floats2half2_rn(f.x, f.y);
            d[1] = __floats2half2_rn(f.z, f.w);
        }
        const float* wp = W + (size_t)(kc + rw) * DD + sw * 8;
        #pragma unroll
        for (int q = 0; q < 2; q++) {
            float4 f = *(const float4*)(wp + q * 4);
            __half2* d = (__half2*)&Ws[rw * 72 + sw * 8 + q * 4];
            d[0] = __floats2half2_rn(f.x, f.y);
            d[1] = __floats2half2_rn(f.z, f.w);
        }
        __syncthreads();
        #pragma unroll
        for (int ks = 0; ks < 2; ks++) {
            uint32_t afr[2][4];
            #pragma unroll
            for (int mm = 0; mm < 2; mm++) {
                int mrow = wm * 32 + mm * 16 + (lane & 15);
                int kcol = ks * 16 + ((lane >> 4) << 3);
                ldm_x4(afr[mm][0], afr[mm][1], afr[mm][2], afr[mm][3],
                       smem_u32(&As[mrow * 40 + kcol]));
            }
            uint32_t bfr[4][2];
            #pragma unroll
            for (int nn = 0; nn < 4; nn++) {
                int krow = ks * 16 + (lane & 15);
                int ncol = wn * 32 + nn * 8;
                ldm_x2t(bfr[nn][0], bfr[nn][1], smem_u32(&Ws[krow * 72 + ncol]));
            }
            #pragma unroll
            for (int mm = 0; mm < 2; mm++)
                #pragma unroll
                for (int nn = 0; nn < 4; nn++)
                    mma16816(acc[mm][nn], afr[mm], bfr[nn]);
        }
        __syncthreads();
    }

    #pragma unroll
    for (int mm = 0; mm < 2; mm++) {
        int r0 = wm * 32 + mm * 16 + (lane >> 2);
        #pragma unroll
        for (int nn = 0; nn < 4; nn++) {
            int c0 = wn * 32 + nn * 8 + (lane & 3) * 2;
            *(float2*)&Cs[r0 * 66 + c0]       = make_float2(acc[mm][nn][0], acc[mm][nn][1]);
            *(float2*)&Cs[(r0 + 8) * 66 + c0] = make_float2(acc[mm][nn][2], acc[mm][nn][3]);
        }
    }
    __syncthreads();

    float2 bv = *(const float2*)&bias[lane * 2];
    #pragma unroll
    for (int i = 0; i < 16; i++) {
        int r = wid * 16 + i;
        int g = rowBase + r;
        if (g >= M) break;
        float2 v = *(const float2*)&Cs[r * 66 + lane * 2];
        v.x += bv.x; v.y += bv.y;
        float ss = v.x * v.x + v.y * v.y;
        #pragma unroll
        for (int o = 16; o; o >>= 1) ss += __shfl_xor_sync(FULL, ss, o);
        float inv = 1.f / fmaxf(sqrtf(ss), 1e-12f);
        size_t off = (size_t)g * DD + lane * 2;
        if (dstf) *(float2*)&dstf[off] = make_float2(v.x * inv, v.y * inv);
        if (dsth) *(__half2*)&dsth[off] =
            __float22half2_rn(make_float2(v.x * inv, v.y * inv));
    }
}

// ---------------- launch 1: FUSED build kernel ----------------
// blocks [0, nb1): img GEMM; [nb1, 2nb1): txt GEMM; rest: scatter + concat.
// img/txt edges go to ONE combined bucket with lambda*w0 / lambda*w1 baked in.
__global__ void k_build(const float* __restrict__ A1, const float* __restrict__ W1,
                        const float* __restrict__ b1, float* __restrict__ XimgI,
                        const float* __restrict__ A2, const float* __restrict__ W2,
                        const float* __restrict__ b2, __half* __restrict__ XthI,
                        int nb1,
                        const int* __restrict__ ar, const int* __restrict__ ac,
                        const float* __restrict__ av,
                        const int* __restrict__ ir, const int* __restrict__ ic,
                        const float* __restrict__ iv,
                        const int* __restrict__ tr, const int* __restrict__ tc,
                        const float* __restrict__ tv,
                        int* __restrict__ cnt, int2* __restrict__ colval,
                        int e0, int e1, int e2,
                        const float* __restrict__ u, const float* __restrict__ it,
                        const float* __restrict__ mw,
                        __half* __restrict__ e0h, __half* __restrict__ e1h,
                        __half* __restrict__ Xth) {
    __shared__ __align__(16) char smu[33792];
    int b = blockIdx.x;
    if (b < 2 * nb1) {
        __half* As = (__half*)smu;
        __half* Ws = (__half*)(smu + 10240);
        float*  Cs = (float*)smu;
        if (b < nb1)
            gemm_body(A1, W1, b1, XimgI, (half*)nullptr, UU, 1024, b, As, Ws, Cs);
        else
            gemm_body(A2, W2, b2, (float*)nullptr, XthI, UU, 384, b - nb1, As, Ws, Cs);
        return;
    }
    int i = (b - 2 * nb1) * blockDim.x + threadIdx.x;

    float a = mw[0], bb = mw[1];
    float mx = fmaxf(a, bb);
    float ea = expf(a - mx), eb = expf(bb - mx);
    float w0l = ea / (ea + eb) * RIS_ADJ_LAMBDA;
    float w1l = eb / (ea + eb) * RIS_ADJ_LAMBDA;

    if (i < e0) {
        int r = ar[i];
        int p = atomicAdd(&cnt[r], 1);
        if (p < CAP)
            colval[(size_t)r * CAP + p] = make_int2(ac[i], __float_as_int(av[i]));
    }
    if (i < e1) {
        int r = ir[i];
        int p = atomicAdd(&cnt[NN + r], 1);
        if (p < CAPC)
            colval[(size_t)NN * CAP + (size_t)r * CAPC + p] =
                make_int2(ic[i], __float_as_int(iv[i] * w0l));
    }
    if (i < e2) {
        int r = tr[i];
        int p = atomicAdd(&cnt[NN + r], 1);
        if (p < CAPC)
            colval[(size_t)NN * CAP + (size_t)r * CAPC + p] =
                make_int2(tc[i], __float_as_int(tv[i] * w1l));
    }
    size_t idx2 = (size_t)i;
    if (idx2 < (size_t)NN * DD / 2) {
        size_t idx = idx2 * 2;
        int n = (int)(idx >> 6);
        if (n < UU) {
            __half2 h = __float22half2_rn(*(const float2*)(u + idx));
            *(__half2*)(e0h + idx) = h;
            *(__half2*)(Xth + idx) = h;
        } else {
            __half2 h = __float22half2_rn(*(const float2*)(it + idx - (size_t)UU * DD));
            *(__half2*)(e0h + idx) = h;
            *(__half2*)(e1h + idx) = h;
        }
    }
}

// ---------------- SpMM core: half-warp per row, float4/lane ----------------
__device__ __forceinline__ float4 spmm16(const int2* __restrict__ colval,
                                         const __half* __restrict__ x,
                                         int s, int len, int mlen, int sub) {
    float4 a0 = make_float4(0.f, 0.f, 0.f, 0.f);
    float4 a1 = make_float4(0.f, 0.f, 0.f, 0.f);
    for (int k = 0; k < mlen; k += 16) {
        int2 cv = (k + sub < len) ? colval[s + k + sub] : make_int2(0, 0);
        #pragma unroll
        for (int j = 0; j < 16; j += 2) {
            int   c0 = __shfl_sync(FULL, cv.x, j, 16);
            float v0 = __int_as_float(__shfl_sync(FULL, cv.y, j, 16));
            int   c1 = __shfl_sync(FULL, cv.x, j + 1, 16);
            float v1 = __int_as_float(__shfl_sync(FULL, cv.y, j + 1, 16));
            float4 x0 = h8_to_f4(*(const uint2*)(x + (size_t)c0 * DD + sub * 4));
            float4 x1 = h8_to_f4(*(const uint2*)(x + (size_t)c1 * DD + sub * 4));
            a0.x = fmaf(v0, x0.x, a0.x); a0.y = fmaf(v0, x0.y, a0.y);
            a0.z = fmaf(v0, x0.z, a0.z); a0.w = fmaf(v0, x0.w, a0.w);
            a1.x = fmaf(v1, x1.x, a1.x); a1.y = fmaf(v1, x1.y, a1.y);
            a1.z = fmaf(v1, x1.z, a1.z); a1.w = fmaf(v1, x1.w, a1.w);
        }
    }
    return make_float4(a0.x + a1.x, a0.y + a1.y, a0.z + a1.z, a0.w + a1.w);
}

// ---------------- launch 2: modality spmms, fused to partial P ---------------
// per row: SC = combined@e0h (= l*w0*S1 + l*w1*S3), (S2,T1) = adj@(e0h,Xth);
// P = w0*(xi + S2) + w1*T1 + SC;  e1h user rows = half(T1).
__global__ void k_spmm_modal(const int* __restrict__ cnt, const int2* __restrict__ colval,
                             const __half* __restrict__ e0h, const __half* __restrict__ Xth,
                             const float* __restrict__ u, const float* __restrict__ XimgI,
                             const float* __restrict__ mw,
                             float* __restrict__ P, __half* __restrict__ e1h) {
    int pair = (blockIdx.x * blockDim.x + threadIdx.x) >> 5;
    if (pair >= NN / 2) return;
    const int lane = threadIdx.x & 31;
    const int half = lane >> 4, sub = lane & 15;
    int row = pair * 2 + half;

    // combined (img+txt, pre-scaled) -> sc
    int len = min(cnt[NN + row], CAPC);
    int mlen = max(len, __shfl_xor_sync(FULL, len, 16));
    float4 sc = spmm16(colval, e0h, NN * CAP + row * CAPC, len, mlen, sub);

    // adj dual -> S2, T1
    len = min(cnt[row], CAP);
    mlen = max(len, __shfl_xor_sync(FULL, len, 16));
    int s = row * CAP;
    float4 p0 = make_float4(0.f,0.f,0.f,0.f), p1 = p0, q0 = p0, q1 = p0;
    for (int k = 0; k < mlen; k += 16) {
        int2 cvv = (k + sub < len) ? colval[(size_t)s + k + sub] : make_int2(0, 0);
        #pragma unroll
        for (int j = 0; j < 16; j += 2) {
            int   c0 = __shfl_sync(FULL, cvv.x, j, 16);
            float v0 = __int_as_float(__shfl_sync(FULL, cvv.y, j, 16));
            int   c1 = __shfl_sync(FULL, cvv.x, j + 1, 16);
            float v1 = __int_as_float(__shfl_sync(FULL, cvv.y, j + 1, 16));
            size_t o0 = (size_t)c0 * DD + sub * 4;
            size_t o1 = (size_t)c1 * DD + sub * 4;
            float4 a0 = h8_to_f4(*(const uint2*)(e0h + o0));
            float4 a1 = h8_to_f4(*(const uint2*)(e0h + o1));
            float4 b0 = (c0 < UU) ? a0 : h8_to_f4(*(const uint2*)(Xth + o0));
            float4 b1 = (c1 < UU) ? a1 : h8_to_f4(*(const uint2*)(Xth + o1));
            p0.x = fmaf(v0, a0.x, p0.x); p0.y = fmaf(v0, a0.y, p0.y);
            p0.z = fmaf(v0, a0.z, p0.z); p0.w = fmaf(v0, a0.w, p0.w);
            p1.x = fmaf(v1, a1.x, p1.x); p1.y = fmaf(v1, a1.y, p1.y);
            p1.z = fmaf(v1, a1.z, p1.z); p1.w = fmaf(v1, a1.w, p1.w);
            q0.x = fmaf(v0, b0.x, q0.x); q0.y = fmaf(v0, b0.y, q0.y);
            q0.z = fmaf(v0, b0.z, q0.z); q0.w = fmaf(v0, b0.w, q0.w);
            q1.x = fmaf(v1, b1.x, q1.x); q1.y = fmaf(v1, b1.y, q1.y);
            q1.z = fmaf(v1, b1.z, q1.z); q1.w = fmaf(v1, b1.w, q1.w);
        }
    }
    float4 s2 = make_float4(p0.x + p1.x, p0.y + p1.y, p0.z + p1.z, p0.w + p1.w);
    float4 t1 = make_float4(q0.x + q1.x, q0.y + q1.y, q0.z + q1.z, q0.w + q1.w);

    float a = mw[0], b = mw[1];
    float mx = fmaxf(a, b);
    float ea = expf(a - mx), eb = expf(b - mx);
    float w0 = ea / (ea + eb), w1 = eb / (ea + eb);
    size_t off = (size_t)row * DD + sub * 4;
    float4 xi = (row < UU) ? *(const float4*)(u + off)
                           : *(const float4*)(XimgI + off - (size_t)UU * DD);
    float4 pv;
    pv.x = w0 * (xi.x + s2.x) + w1 * t1.x + sc.x;
    pv.y = w0 * (xi.y + s2.y) + w1 * t1.y + sc.y;
    pv.z = w0 * (xi.z + s2.z) + w1 * t1.z + sc.z;
    pv.w = w0 * (xi.w + s2.w) + w1 * t1.w + sc.w;
    *(float4*)(P + off) = pv;
    if (row < UU) *(uint2*)(e1h + off) = f4_to_h8(t1);
}

// ---------------- launch 3: T2 spmm + final modal ----------------------------
__global__ void k_spmmT2_modal(const int* __restrict__ cnt,
                               const int2* __restrict__ colval,
                               const __half* __restrict__ x,
                               const float* __restrict__ P,
                               const float* __restrict__ mw,
                               float* __restrict__ modal,
                               __half* __restrict__ modalh) {
    int pair = (blockIdx.x * blockDim.x + threadIdx.x) >> 5;
    if (pair >= NN / 2) return;
    const int lane = threadIdx.x & 31;
    const int half = lane >> 4, sub = lane & 15;
    int row = pair * 2 + half;
    int len = min(cnt[row], CAP);
    int mlen = max(len, __shfl_xor_sync(FULL, len, 16));
    float4 t2 = spmm16(colval, x, row * CAP, len, mlen, sub);

    float a = mw[0], b = mw[1];
    float mx = fmaxf(a, b);
    float ea = expf(a - mx), eb = expf(b - mx);
    float w1 = eb / (ea + eb);

    size_t off = (size_t)row * DD + sub * 4;
    float4 pv = *(const float4*)(P + off);
    float4 m = make_float4(pv.x + w1 * t2.x, pv.y + w1 * t2.y,
                           pv.z + w1 * t2.z, pv.w + w1 * t2.w);
    *(float4*)(modal + off) = m;
    *(uint2*)(modalh + off) = f4_to_h8(m);
}

// ---------------- GNN spmm: y(fp16) = adj@x + attention scores ----------------
__global__ void k_spmm(const int* __restrict__ cnt, const int2* __restrict__ colval,
                       const __half* __restrict__ x, __half* __restrict__ y,
                       const float* __restrict__ attw, float* __restrict__ scores) {
    int pair = (blockIdx.x * blockDim.x + threadIdx.x) >> 5;
    if (pair >= NN / 2) return;
    const int lane = threadIdx.x & 31;
    const int half = lane >> 4, sub = lane & 15;
    int row = pair * 2 + half;
    int len = min(cnt[row], CAP);
    int mlen = max(len, __shfl_xor_sync(FULL, len, 16));
    float4 acc = spmm16(colval, x, row * CAP, len, mlen, sub);
    *(uint2*)(y + (size_t)row * DD + sub * 4) = f4_to_h8(acc);
    float4 aw = *(const float4*)(attw + sub * 4);
    float sc = acc.x * aw.x + acc.y * aw.y + acc.z * aw.z + acc.w * aw.w;
    #pragma unroll
    for (int o = 8; o; o >>= 1) sc += __shfl_xor_sync(FULL, sc, o, 16);
    if (sub == 0) scores[row] = sc;
}

// ---------------- softmax partials ----------------
__global__ void k_redpart(const float* __restrict__ scores, float* __restrict__ part) {
    const int tid = threadIdx.x, lane = tid & 31, wid = tid >> 5;
    float m = -3.4e38f, s = 0.f;
    for (int i = blockIdx.x * blockDim.x + tid; i < NN; i += gridDim.x * blockDim.x) {
        float x = scores[i];
        float M = fmaxf(m, x);
        s = s * expf(m - M) + expf(x - M);
        m = M;
    }
    #pragma unroll
    for (int o = 16; o; o >>= 1) {
        float m2 = __shfl_xor_sync(FULL, m, o);
        float s2 = __shfl_xor_sync(FULL, s, o);
        msmerge(m, s, m2, s2);
    }
    __shared__ float sm[8], ssum[8];
    if (lane == 0) { sm[wid] = m; ssum[wid] = s; }
    __syncthreads();
    if (tid == 0) {
        float M = sm[0], S = ssum[0];
        #pragma unroll
        for (int w = 1; w < 8; w++) msmerge(M, S, sm[w], ssum[w]);
        part[blockIdx.x * 2]     = M;
        part[blockIdx.x * 2 + 1] = S;
    }
}

__device__ __forceinline__ void merge_partials(const float* __restrict__ part,
                                               float& M, float& S,
                                               float* sMS, int tid) {
    if (tid < 32) {
        float m = -3.4e38f, s = 0.f;
        #pragma unroll
        for (int i = tid; i < NPART; i += 32)
            msmerge(m, s, part[i * 2], part[i * 2 + 1]);
        #pragma unroll
        for (int o = 16; o; o >>= 1) {
            float m2 = __shfl_xor_sync(FULL, m, o);
            float s2 = __shfl_xor_sync(FULL, s, o);
            msmerge(m, s, m2, s2);
        }
        if (tid == 0) { sMS[0] = m; sMS[1] = s; }
    }
    __syncthreads();
    M = sMS[0]; S = sMS[1];
}

// layer-1 apply: ch = half(leakyrelu(E*att)); 4 halves/thread
__global__ void k_apply(const __half* __restrict__ e, const float* __restrict__ scores,
                        const float* __restrict__ part, __half* __restrict__ curh) {
    __shared__ float sMS[2];
    float M, S;
    merge_partials(part, M, S, sMS, threadIdx.x);
    size_t i4 = (size_t)blockIdx.x * blockDim.x + threadIdx.x;
    if (i4 >= (size_t)NN * DD / 4) return;
    size_t idx = i4 * 4;
    int n = (int)(idx >> 6);
    float att = expf(scores[n] - M) / S;
    float4 v = h8_to_f4(*(const uint2*)(e + idx));
    v.x *= att; v.x = (v.x > 0.f) ? v.x : LEAK * v.x;
    v.y *= att; v.y = (v.y > 0.f) ? v.y : LEAK * v.y;
    v.z *= att; v.z = (v.z > 0.f) ? v.z : LEAK * v.z;
    v.w *= att; v.w = (v.w > 0.f) ? v.w : LEAK * v.w;
    *(uint2*)(curh + idx) = f4_to_h8(v);
}

// layer-2 apply fused with final output; also re-zeroes cnt for the next replay
__global__ void k_apply2_final(const __half* __restrict__ e, const float* __restrict__ scores,
                               const float* __restrict__ part,
                               const __half* __restrict__ lay1,
                               const float* __restrict__ modal,
                               float* __restrict__ out) {
    __shared__ float sMS[2];
    float M, S;
    merge_partials(part, M, S, sMS, threadIdx.x);
    int gid = blockIdx.x * blockDim.x + threadIdx.x;
    if (gid < 2 * NN) g_cnt[gid] = 0;        // reset bucket counters for next run
    int row = gid >> 5;
    if (row >= NN) return;
    const int lane = threadIdx.x & 31;
    size_t off = (size_t)row * DD + lane * 2;
    float att = expf(scores[row] - M) / S;
    float2 ev = __half22float2(*(const __half2*)(e + off));
    float vx = ev.x * att; vx = (vx > 0.f) ? vx : LEAK * vx;
    float vy = ev.y * att; vy = (vy > 0.f) ? vy : LEAK * vy;
    float2 l1 = __half22float2(*(const __half2*)(lay1 + off));
    float2 m = *(const float2*)(modal + off);
    float ss = m.x * m.x + m.y * m.y;
    #pragma unroll
    for (int o = 16; o; o >>= 1) ss += __shfl_xor_sync(FULL, ss, o);
    float inv = 1.f / fmaxf(sqrtf(ss), 1e-12f);
    *(float2*)(out + off) = make_float2(m.x + l1.x + vx + RIS_LAMBDA * m.x * inv,
                                        m.y + l1.y + vy + RIS_LAMBDA * m.y * inv);
}

// ---------------- host ----------------
extern "C" void kernel_launch(void* const* d_in, const int* in_sizes, int n_in,
                              void* d_out, int out_size) {
    const int*   adj_rows = (const int*)d_in[0];
    const int*   adj_cols = (const int*)d_in[1];
    const float* adj_vals = (const float*)d_in[2];
    const int*   img_rows = (const int*)d_in[3];
    const int*   img_cols = (const int*)d_in[4];
    const float* img_vals = (const float*)d_in[5];
    const int*   txt_rows = (const int*)d_in[6];
    const int*   txt_cols = (const int*)d_in[7];
    const float* txt_vals = (const float*)d_in[8];
    const float* u_emb    = (const float*)d_in[9];
    const float* i_emb    = (const float*)d_in[10];
    const float* img_W    = (const float*)d_in[11];
    const float* img_b    = (const float*)d_in[12];
    const float* txt_W    = (const float*)d_in[13];
    const float* txt_b    = (const float*)d_in[14];
    const float* modal_w  = (const float*)d_in[15];
    const float* att_w    = (const float*)d_in[16];
    const float* image_embedding = (const float*)d_in[17];
    const float* text_embedding  = (const float*)d_in[18];

    const int Eadj = in_sizes[0], Eimg = in_sizes[3], Etxt = in_sizes[6];
    int Emx = Eadj > Eimg ? Eadj : Eimg;
    if (Etxt > Emx) Emx = Etxt;
    long long fuse_n = (long long)NN * DD / 2;
    if ((long long)Emx > fuse_n) fuse_n = Emx;

    __half *e0h, *e1h, *Xth, *mh, *ch, *Eh;
    float *XimgI, *P, *modal;
    float *scores, *part;
    int *cnt;
    int2 *colval;
    cudaGetSymbolAddress((void**)&e0h,   g_e0h);
    cudaGetSymbolAddress((void**)&e1h,   g_e1h);
    cudaGetSymbolAddress((void**)&Xth,   g_Xth);
    cudaGetSymbolAddress((void**)&mh,    g_mh);
    cudaGetSymbolAddress((void**)&ch,    g_ch);
    cudaGetSymbolAddress((void**)&Eh,    g_Eh);
    cudaGetSymbolAddress((void**)&XimgI, g_XimgI);
    cudaGetSymbolAddress((void**)&P,     g_P);
    cudaGetSymbolAddress((void**)&modal, g_modal);
    cudaGetSymbolAddress((void**)&scores,g_scores);
    cudaGetSymbolAddress((void**)&part,  g_redpart);
    cudaGetSymbolAddress((void**)&cnt,   g_cnt);
    cudaGetSymbolAddress((void**)&colval,g_colval);

    const int TPB = 256;
    const int ew4_blocks   = (NN * DD / 4 + TPB - 1) / TPB;   // 6250
    const int row_blocks   = (NN * 32 + TPB - 1) / TPB;       // 12500
    const int fuse_blocks  = (int)((fuse_n + TPB - 1) / TPB);
    const int nb1 = (UU + 127) / 128;

    // 1: FUSED build: 2 GEMMs + scatter/concat (cnt pre-zeroed: load-time init
    //    on first run, re-zeroed by k_apply2_final on every run thereafter)
    k_build<<<2 * nb1 + fuse_blocks, TPB>>>(
        image_embedding, img_W, img_b, XimgI,
        text_embedding, txt_W, txt_b, Xth + (size_t)UU * DD, nb1,
        adj_rows, adj_cols, adj_vals,
        img_rows, img_cols, img_vals,
        txt_rows, txt_cols, txt_vals,
        cnt, colval, Eadj, Eimg, Etxt,
        u_emb, i_emb, modal_w, e0h, e1h, Xth);
    // 2: modality spmms (combined + adj-dual) fused to partial P (+ e1h)
    k_spmm_modal<<<PAIRB, TPB>>>(cnt, colval, e0h, Xth, u_emb, XimgI,
                                 modal_w, P, e1h);
    // 3: T2 spmm + final modal (+ mh)
    k_spmmT2_modal<<<PAIRB, TPB>>>(cnt, colval, e1h, P, modal_w, modal, mh);
    // 4-6: GNN layer 1
    k_spmm<<<PAIRB, TPB>>>(cnt, colval, mh, Eh, att_w + 0, scores);
    k_redpart<<<NPART, 256>>>(scores, part);
    k_apply<<<ew4_blocks, TPB>>>(Eh, scores, part, ch);
    // 7-9: GNN layer 2 + fused final (also resets cnt)
    k_spmm<<<PAIRB, TPB>>>(cnt, colval, ch, Eh, att_w + DD, scores);
    k_redpart<<<NPART, 256>>>(scores, part);
    k_apply2_final<<<row_blocks, TPB>>>(Eh, scores, part, ch, modal, (float*)d_out);
}